// round 1
// baseline (speedup 1.0000x reference)
#include <cuda_runtime.h>
#include <math.h>

#define TOK 4096
#define HID 1024
#define FFN 4096
#define NE  8
#define NPART 64

// ---------------- device scratch (static; no allocation) ----------------
__device__ float g_probsum_part[NE * NPART];
__device__ int   g_counts_part[NE * NPART];
__device__ int   g_offsets[NE + 1];
__device__ int   g_cursor[NE];
__device__ int   g_perm[TOK];      // perm[slot] = token id
__device__ int   g_expert[TOK];    // expert of token
__device__ float g_gate[TOK];      // gate weight of token
__device__ float g_xg[(size_t)TOK * HID];      // gathered inputs (expert-contiguous)
__device__ float g_h[(size_t)TOK * FFN];       // GEMM1 output (64 MB)

// ---------------- init ----------------
__global__ void init_kernel() {
    int i = blockIdx.x * blockDim.x + threadIdx.x;
    if (i < NE * NPART) { g_probsum_part[i] = 0.f; g_counts_part[i] = 0; }
}

// ---------------- router: logits, softmax, top-1, partitioned stats ----------------
__global__ __launch_bounds__(256) void router_kernel(const float* __restrict__ x,
                                                     const float* __restrict__ rw) {
    int t = blockIdx.x;
    __shared__ float xs[HID];
    __shared__ float lg[NE];
    // stage x row (256 thr * 4 floats)
    const float4* x4 = (const float4*)(x + (size_t)t * HID);
    ((float4*)xs)[threadIdx.x] = x4[threadIdx.x];
    __syncthreads();

    int w = threadIdx.x >> 5, lane = threadIdx.x & 31;
    const float* rwe = rw + w * HID;
    float s = 0.f;
    #pragma unroll 8
    for (int i = lane; i < HID; i += 32) s += xs[i] * rwe[i];
    #pragma unroll
    for (int o = 16; o; o >>= 1) s += __shfl_xor_sync(0xffffffffu, s, o);
    if (lane == 0) lg[w] = s;
    __syncthreads();

    if (threadIdx.x == 0) {
        float mx = lg[0]; int idx = 0;
        #pragma unroll
        for (int e = 1; e < NE; e++) if (lg[e] > mx) { mx = lg[e]; idx = e; }
        float p[NE]; float den = 0.f;
        #pragma unroll
        for (int e = 0; e < NE; e++) { p[e] = expf(lg[e] - mx); den += p[e]; }
        float inv = 1.f / den;
        int part = t & (NPART - 1);
        #pragma unroll
        for (int e = 0; e < NE; e++) atomicAdd(&g_probsum_part[e * NPART + part], p[e] * inv);
        g_gate[t] = p[idx] * inv;
        g_expert[t] = idx;
        atomicAdd(&g_counts_part[idx * NPART + part], 1);
    }
}

// ---------------- prefix: reduce partitions, scan, aux loss ----------------
__global__ void prefix_kernel(float* __restrict__ out, int out_size) {
    __shared__ float ps[NE];
    __shared__ int   cs[NE];
    int tid = threadIdx.x;
    if (tid < NE) {
        float s = 0.f; int c = 0;
        for (int p = 0; p < NPART; p++) {
            s += g_probsum_part[tid * NPART + p];
            c += g_counts_part[tid * NPART + p];
        }
        ps[tid] = s; cs[tid] = c;
    }
    __syncthreads();
    if (tid == 0) {
        int run = 0; float aux = 0.f;
        for (int e = 0; e < NE; e++) {
            g_offsets[e] = run; g_cursor[e] = run;
            run += cs[e];
            aux += ps[e] * (float)cs[e];
        }
        g_offsets[NE] = run;
        aux *= 0.01f * (float)NE / ((float)TOK * (float)TOK);
        if (out_size > TOK * HID) out[TOK * HID] = aux;
    }
}

// ---------------- gather tokens into expert-contiguous layout ----------------
__global__ __launch_bounds__(256) void gather_kernel(const float* __restrict__ x) {
    int t = blockIdx.x;
    __shared__ int slot_s;
    if (threadIdx.x == 0) {
        int e = g_expert[t];
        int slot = atomicAdd(&g_cursor[e], 1);
        g_perm[slot] = t;
        slot_s = slot;
    }
    __syncthreads();
    int slot = slot_s;
    const float4* src = (const float4*)(x + (size_t)t * HID);
    float4* dst = (float4*)(g_xg + (size_t)slot * HID);
    dst[threadIdx.x] = src[threadIdx.x];   // 256 * 4 = 1024
}

__device__ __forceinline__ float gelu_exact(float v) {
    return 0.5f * v * (1.0f + erff(v * 0.70710678118654752f));
}

// ---------------- grouped GEMM1: h = gelu(Xe @ W1e^T + b1e) ----------------
// C[ne, FFN], A = g_xg (row-major, K=HID), B = fc1_w[e] (FFN rows, K=HID) : NT layout
#define BM 64
#define BN 64
#define BK 16

__global__ __launch_bounds__(256) void gemm1_kernel(const float* __restrict__ fc1_w,
                                                    const float* __restrict__ fc1_b) {
    int e = blockIdx.z;
    int off = g_offsets[e];
    int ne  = g_offsets[e + 1] - off;
    int m0  = blockIdx.y * BM;
    if (m0 >= ne) return;
    int n0 = blockIdx.x * BN;

    const float* A = g_xg + (size_t)off * HID;
    const float* B = fc1_w + (size_t)e * FFN * HID;

    __shared__ float As[BK][BM];
    __shared__ float Bs[BK][BN];

    int tid = threadIdx.x;
    int tx = tid & 15, ty = tid >> 4;
    int lr = tid >> 2;            // 0..63: tile row
    int lc = (tid & 3) * 4;       // k offset within BK

    float acc[4][4] = {};

    int arow = m0 + lr;
    bool avalid = arow < ne;
    const float* aptr = A + (size_t)(avalid ? arow : 0) * HID + lc;
    const float* bptr = B + (size_t)(n0 + lr) * HID + lc;

    for (int k0 = 0; k0 < HID; k0 += BK) {
        float4 av = avalid ? *(const float4*)(aptr + k0) : make_float4(0.f, 0.f, 0.f, 0.f);
        float4 bv = *(const float4*)(bptr + k0);
        As[lc + 0][lr] = av.x; As[lc + 1][lr] = av.y; As[lc + 2][lr] = av.z; As[lc + 3][lr] = av.w;
        Bs[lc + 0][lr] = bv.x; Bs[lc + 1][lr] = bv.y; Bs[lc + 2][lr] = bv.z; Bs[lc + 3][lr] = bv.w;
        __syncthreads();
        #pragma unroll
        for (int k = 0; k < BK; k++) {
            float4 a = *(const float4*)&As[k][ty * 4];
            float4 b = *(const float4*)&Bs[k][tx * 4];
            float ar[4] = {a.x, a.y, a.z, a.w};
            float br[4] = {b.x, b.y, b.z, b.w};
            #pragma unroll
            for (int i = 0; i < 4; i++)
                #pragma unroll
                for (int j = 0; j < 4; j++)
                    acc[i][j] = fmaf(ar[i], br[j], acc[i][j]);
        }
        __syncthreads();
    }

    const float* bb = fc1_b + (size_t)e * FFN + n0 + tx * 4;
    float b4[4] = {bb[0], bb[1], bb[2], bb[3]};
    #pragma unroll
    for (int i = 0; i < 4; i++) {
        int m = m0 + ty * 4 + i;
        if (m < ne) {
            float4 o;
            o.x = gelu_exact(acc[i][0] + b4[0]);
            o.y = gelu_exact(acc[i][1] + b4[1]);
            o.z = gelu_exact(acc[i][2] + b4[2]);
            o.w = gelu_exact(acc[i][3] + b4[3]);
            *(float4*)(g_h + (size_t)(off + m) * FFN + n0 + tx * 4) = o;
        }
    }
}

// ---------------- grouped GEMM2: out = (He @ W2e^T + b2e) * gate, scattered ----------------
// C[ne, HID], A = g_h (K=FFN), B = fc2_w[e] (HID rows, K=FFN)
__global__ __launch_bounds__(256) void gemm2_kernel(const float* __restrict__ fc2_w,
                                                    const float* __restrict__ fc2_b,
                                                    float* __restrict__ out) {
    int e = blockIdx.z;
    int off = g_offsets[e];
    int ne  = g_offsets[e + 1] - off;
    int m0  = blockIdx.y * BM;
    if (m0 >= ne) return;
    int n0 = blockIdx.x * BN;

    const float* A = g_h + (size_t)off * FFN;
    const float* B = fc2_w + (size_t)e * HID * FFN;

    __shared__ float As[BK][BM];
    __shared__ float Bs[BK][BN];

    int tid = threadIdx.x;
    int tx = tid & 15, ty = tid >> 4;
    int lr = tid >> 2;
    int lc = (tid & 3) * 4;

    float acc[4][4] = {};

    int arow = m0 + lr;
    bool avalid = arow < ne;
    const float* aptr = A + (size_t)(avalid ? arow : 0) * FFN + lc;
    const float* bptr = B + (size_t)(n0 + lr) * FFN + lc;

    for (int k0 = 0; k0 < FFN; k0 += BK) {
        float4 av = avalid ? *(const float4*)(aptr + k0) : make_float4(0.f, 0.f, 0.f, 0.f);
        float4 bv = *(const float4*)(bptr + k0);
        As[lc + 0][lr] = av.x; As[lc + 1][lr] = av.y; As[lc + 2][lr] = av.z; As[lc + 3][lr] = av.w;
        Bs[lc + 0][lr] = bv.x; Bs[lc + 1][lr] = bv.y; Bs[lc + 2][lr] = bv.z; Bs[lc + 3][lr] = bv.w;
        __syncthreads();
        #pragma unroll
        for (int k = 0; k < BK; k++) {
            float4 a = *(const float4*)&As[k][ty * 4];
            float4 b = *(const float4*)&Bs[k][tx * 4];
            float ar[4] = {a.x, a.y, a.z, a.w};
            float br[4] = {b.x, b.y, b.z, b.w};
            #pragma unroll
            for (int i = 0; i < 4; i++)
                #pragma unroll
                for (int j = 0; j < 4; j++)
                    acc[i][j] = fmaf(ar[i], br[j], acc[i][j]);
        }
        __syncthreads();
    }

    const float* bb = fc2_b + (size_t)e * HID + n0 + tx * 4;
    float b4[4] = {bb[0], bb[1], bb[2], bb[3]};
    #pragma unroll
    for (int i = 0; i < 4; i++) {
        int m = m0 + ty * 4 + i;
        if (m < ne) {
            int tok = g_perm[off + m];
            float gate = g_gate[tok];
            float4 o;
            o.x = (acc[i][0] + b4[0]) * gate;
            o.y = (acc[i][1] + b4[1]) * gate;
            o.z = (acc[i][2] + b4[2]) * gate;
            o.w = (acc[i][3] + b4[3]) * gate;
            *(float4*)(out + (size_t)tok * HID + n0 + tx * 4) = o;
        }
    }
}

// ---------------- launch ----------------
extern "C" void kernel_launch(void* const* d_in, const int* in_sizes, int n_in,
                              void* d_out, int out_size) {
    const float* x        = (const float*)d_in[0];
    const float* router_w = (const float*)d_in[1];
    const float* fc1_w    = (const float*)d_in[2];
    const float* fc1_b    = (const float*)d_in[3];
    const float* fc2_w    = (const float*)d_in[4];
    const float* fc2_b    = (const float*)d_in[5];
    float* out = (float*)d_out;

    init_kernel<<<(NE * NPART + 255) / 256, 256>>>();
    router_kernel<<<TOK, 256>>>(x, router_w);
    prefix_kernel<<<1, 256>>>(out, out_size);
    gather_kernel<<<TOK, 256>>>(x);

    dim3 g1(FFN / BN, TOK / BM, NE);   // 64 x 64 x 8 (early-exit tiles)
    gemm1_kernel<<<g1, 256>>>(fc1_w, fc1_b);

    dim3 g2(HID / BN, TOK / BM, NE);   // 16 x 64 x 8
    gemm2_kernel<<<g2, 256>>>(fc2_w, fc2_b, out);
}

// round 2
// speedup vs baseline: 3.3460x; 3.3460x over previous
#include <cuda_runtime.h>
#include <math.h>
#include <stdint.h>

#define TOK 4096
#define HID 1024
#define FFN 4096
#define NE  8
#define NPART 64

#define BM 128
#define BN 128
#define BK 16
#define PAD 4
#define KROW (BK + PAD)

// ---------------- device scratch (static; no allocation) ----------------
__device__ float g_probsum_part[NE * NPART];
__device__ int   g_counts_part[NE * NPART];
__device__ int   g_offsets[NE + 1];
__device__ int   g_cursor[NE];
__device__ int   g_perm[TOK];
__device__ int   g_expert[TOK];
__device__ float g_gate[TOK];
// +BM zero rows of padding so GEMM tiles can read past segment ends safely
__device__ float g_xg[(size_t)(TOK + BM) * HID];
__device__ float g_h[(size_t)(TOK + BM) * FFN];

// ---------------- init ----------------
__global__ void init_kernel() {
    int i = blockIdx.x * blockDim.x + threadIdx.x;
    if (i < NE * NPART) { g_probsum_part[i] = 0.f; g_counts_part[i] = 0; }
}

// ---------------- router ----------------
__global__ __launch_bounds__(256) void router_kernel(const float* __restrict__ x,
                                                     const float* __restrict__ rw) {
    int t = blockIdx.x;
    __shared__ float xs[HID];
    __shared__ float lg[NE];
    const float4* x4 = (const float4*)(x + (size_t)t * HID);
    ((float4*)xs)[threadIdx.x] = x4[threadIdx.x];
    __syncthreads();

    int w = threadIdx.x >> 5, lane = threadIdx.x & 31;
    const float* rwe = rw + w * HID;
    float s = 0.f;
    #pragma unroll 8
    for (int i = lane; i < HID; i += 32) s += xs[i] * rwe[i];
    #pragma unroll
    for (int o = 16; o; o >>= 1) s += __shfl_xor_sync(0xffffffffu, s, o);
    if (lane == 0) lg[w] = s;
    __syncthreads();

    if (threadIdx.x == 0) {
        float mx = lg[0]; int idx = 0;
        #pragma unroll
        for (int e = 1; e < NE; e++) if (lg[e] > mx) { mx = lg[e]; idx = e; }
        float p[NE]; float den = 0.f;
        #pragma unroll
        for (int e = 0; e < NE; e++) { p[e] = expf(lg[e] - mx); den += p[e]; }
        float inv = 1.f / den;
        int part = t & (NPART - 1);
        #pragma unroll
        for (int e = 0; e < NE; e++) atomicAdd(&g_probsum_part[e * NPART + part], p[e] * inv);
        g_gate[t] = p[idx] * inv;
        g_expert[t] = idx;
        atomicAdd(&g_counts_part[idx * NPART + part], 1);
    }
}

// ---------------- prefix ----------------
__global__ void prefix_kernel(float* __restrict__ out, int out_size) {
    __shared__ float ps[NE];
    __shared__ int   cs[NE];
    int tid = threadIdx.x;
    if (tid < NE) {
        float s = 0.f; int c = 0;
        for (int p = 0; p < NPART; p++) {
            s += g_probsum_part[tid * NPART + p];
            c += g_counts_part[tid * NPART + p];
        }
        ps[tid] = s; cs[tid] = c;
    }
    __syncthreads();
    if (tid == 0) {
        int run = 0; float aux = 0.f;
        for (int e = 0; e < NE; e++) {
            g_offsets[e] = run; g_cursor[e] = run;
            run += cs[e];
            aux += ps[e] * (float)cs[e];
        }
        g_offsets[NE] = run;
        aux *= 0.01f * (float)NE / ((float)TOK * (float)TOK);
        if (out_size > TOK * HID) out[TOK * HID] = aux;
    }
}

// ---------------- gather ----------------
__global__ __launch_bounds__(256) void gather_kernel(const float* __restrict__ x) {
    int t = blockIdx.x;
    __shared__ int slot_s;
    if (threadIdx.x == 0) {
        int e = g_expert[t];
        int slot = atomicAdd(&g_cursor[e], 1);
        g_perm[slot] = t;
        slot_s = slot;
    }
    __syncthreads();
    int slot = slot_s;
    const float4* src = (const float4*)(x + (size_t)t * HID);
    float4* dst = (float4*)(g_xg + (size_t)slot * HID);
    dst[threadIdx.x] = src[threadIdx.x];
}

// ---------------- helpers ----------------
__device__ __forceinline__ float gelu_exact(float v) {
    return 0.5f * v * (1.0f + erff(v * 0.70710678118654752f));
}
__device__ __forceinline__ uint32_t cvt_tf32(float f) {
    uint32_t u; asm("cvt.rna.tf32.f32 %0, %1;" : "=r"(u) : "f"(f)); return u;
}
__device__ __forceinline__ void cp16(uint32_t saddr, const void* g) {
    asm volatile("cp.async.cg.shared.global [%0], [%1], 16;" :: "r"(saddr), "l"(g));
}
__device__ __forceinline__ void mma_tf32(float c[4], const uint32_t a[4], const uint32_t b[2]) {
    asm volatile("mma.sync.aligned.m16n8k8.row.col.f32.tf32.tf32.f32 "
        "{%0,%1,%2,%3}, {%4,%5,%6,%7}, {%8,%9}, {%0,%1,%2,%3};"
        : "+f"(c[0]), "+f"(c[1]), "+f"(c[2]), "+f"(c[3])
        : "r"(a[0]), "r"(a[1]), "r"(a[2]), "r"(a[3]), "r"(b[0]), "r"(b[1]));
}

// ---------------- grouped tensor-core GEMM ----------------
// IS_FC1: A=g_xg [K=HID], B=fc1_w rows, epilogue gelu -> g_h
// else:   A=g_h  [K=FFN], B=fc2_w rows, epilogue gate-scatter -> out
template<int KDIM, bool IS_FC1>
__global__ __launch_bounds__(256) void gemm_tc(const float* __restrict__ W,
                                               const float* __restrict__ bias,
                                               float* __restrict__ outp) {
    int e = blockIdx.z;
    int off = g_offsets[e];
    int ne  = g_offsets[e + 1] - off;
    int m0  = blockIdx.y * BM;
    if (m0 >= ne) return;
    int n0 = blockIdx.x * BN;

    const int NDIM = IS_FC1 ? FFN : HID;
    const float* A = (IS_FC1 ? g_xg : g_h) + (size_t)(off + m0) * KDIM;
    const float* B = W + (size_t)e * NDIM * KDIM + (size_t)n0 * KDIM;

    __shared__ float As[2][BM][KROW];
    __shared__ float Bs[2][BN][KROW];

    int tid = threadIdx.x;
    int r  = tid >> 2;          // 0..63
    int kq = (tid & 3) * 4;     // 0,4,8,12

    uint32_t sa0 = (uint32_t)__cvta_generic_to_shared(&As[0][r][kq]);
    uint32_t sa1 = (uint32_t)__cvta_generic_to_shared(&As[0][r + 64][kq]);
    uint32_t sb0 = (uint32_t)__cvta_generic_to_shared(&Bs[0][r][kq]);
    uint32_t sb1 = (uint32_t)__cvta_generic_to_shared(&Bs[0][r + 64][kq]);
    const uint32_t STG = BM * KROW * sizeof(float);   // stage stride

    const float* Ar0 = A + (size_t)r * KDIM + kq;
    const float* Ar1 = A + (size_t)(r + 64) * KDIM + kq;
    const float* Br0 = B + (size_t)r * KDIM + kq;
    const float* Br1 = B + (size_t)(r + 64) * KDIM + kq;

    // prefetch stage 0
    cp16(sa0, Ar0); cp16(sa1, Ar1);
    cp16(sb0, Br0); cp16(sb1, Br1);
    asm volatile("cp.async.commit_group;" ::: "memory");

    int wid = tid >> 5, lane = tid & 31;
    int wm = wid & 3;        // 0..3 -> m offset wm*32
    int wn = wid >> 2;       // 0..1 -> n offset wn*64
    int g  = lane >> 2;      // 0..7
    int t4 = lane & 3;       // 0..3

    float acc[2][8][4] = {};

    const int KT = KDIM / BK;
    for (int kt = 0; kt < KT; kt++) {
        int s = kt & 1;
        if (kt + 1 < KT) {
            int ns = (kt + 1) & 1;
            int ko = (kt + 1) * BK;
            cp16(sa0 + ns * STG, Ar0 + ko); cp16(sa1 + ns * STG, Ar1 + ko);
            cp16(sb0 + ns * STG, Br0 + ko); cp16(sb1 + ns * STG, Br1 + ko);
            asm volatile("cp.async.commit_group;" ::: "memory");
            asm volatile("cp.async.wait_group 1;" ::: "memory");
        } else {
            asm volatile("cp.async.wait_group 0;" ::: "memory");
        }
        __syncthreads();

        #pragma unroll
        for (int ks = 0; ks < 2; ks++) {
            int kb = ks * 8;
            uint32_t a[2][4];
            #pragma unroll
            for (int i = 0; i < 2; i++) {
                int rm = wm * 32 + i * 16 + g;
                a[i][0] = cvt_tf32(As[s][rm][kb + t4]);
                a[i][1] = cvt_tf32(As[s][rm + 8][kb + t4]);
                a[i][2] = cvt_tf32(As[s][rm][kb + t4 + 4]);
                a[i][3] = cvt_tf32(As[s][rm + 8][kb + t4 + 4]);
            }
            uint32_t b[8][2];
            #pragma unroll
            for (int j = 0; j < 8; j++) {
                int rn = wn * 64 + j * 8 + g;
                b[j][0] = cvt_tf32(Bs[s][rn][kb + t4]);
                b[j][1] = cvt_tf32(Bs[s][rn][kb + t4 + 4]);
            }
            #pragma unroll
            for (int i = 0; i < 2; i++)
                #pragma unroll
                for (int j = 0; j < 8; j++)
                    mma_tf32(acc[i][j], a[i], b[j]);
        }
        __syncthreads();
    }

    // ---------------- epilogue ----------------
    #pragma unroll
    for (int i = 0; i < 2; i++) {
        int rml = wm * 32 + i * 16 + g;         // local row for c0/c1; +8 for c2/c3
        #pragma unroll
        for (int j = 0; j < 8; j++) {
            int col = n0 + wn * 64 + j * 8 + 2 * t4;
            if (IS_FC1) {
                float b0v = bias[(size_t)e * FFN + col];
                float b1v = bias[(size_t)e * FFN + col + 1];
                int m_ = m0 + rml;
                if (m_ < ne) {
                    float2 o;
                    o.x = gelu_exact(acc[i][j][0] + b0v);
                    o.y = gelu_exact(acc[i][j][1] + b1v);
                    *(float2*)&g_h[(size_t)(off + m_) * FFN + col] = o;
                }
                if (m_ + 8 < ne) {
                    float2 o;
                    o.x = gelu_exact(acc[i][j][2] + b0v);
                    o.y = gelu_exact(acc[i][j][3] + b1v);
                    *(float2*)&g_h[(size_t)(off + m_ + 8) * FFN + col] = o;
                }
            } else {
                float b0v = bias[(size_t)e * HID + col];
                float b1v = bias[(size_t)e * HID + col + 1];
                int m_ = m0 + rml;
                if (m_ < ne) {
                    int tok = g_perm[off + m_];
                    float gt = g_gate[tok];
                    float2 o;
                    o.x = (acc[i][j][0] + b0v) * gt;
                    o.y = (acc[i][j][1] + b1v) * gt;
                    *(float2*)&outp[(size_t)tok * HID + col] = o;
                }
                if (m_ + 8 < ne) {
                    int tok = g_perm[off + m_ + 8];
                    float gt = g_gate[tok];
                    float2 o;
                    o.x = (acc[i][j][2] + b0v) * gt;
                    o.y = (acc[i][j][3] + b1v) * gt;
                    *(float2*)&outp[(size_t)tok * HID + col] = o;
                }
            }
        }
    }
}

// ---------------- launch ----------------
extern "C" void kernel_launch(void* const* d_in, const int* in_sizes, int n_in,
                              void* d_out, int out_size) {
    const float* x        = (const float*)d_in[0];
    const float* router_w = (const float*)d_in[1];
    const float* fc1_w    = (const float*)d_in[2];
    const float* fc1_b    = (const float*)d_in[3];
    const float* fc2_w    = (const float*)d_in[4];
    const float* fc2_b    = (const float*)d_in[5];
    float* out = (float*)d_out;

    init_kernel<<<(NE * NPART + 255) / 256, 256>>>();
    router_kernel<<<TOK, 256>>>(x, router_w);
    prefix_kernel<<<1, 256>>>(out, out_size);
    gather_kernel<<<TOK, 256>>>(x);

    dim3 g1(FFN / BN, TOK / BM, NE);   // 32 x 32 x 8, early-exit tiles
    gemm_tc<HID, true><<<g1, 256>>>(fc1_w, fc1_b, nullptr);

    dim3 g2(HID / BN, TOK / BM, NE);   // 8 x 32 x 8
    gemm_tc<FFN, false><<<g2, 256>>>(fc2_w, fc2_b, out);
}

// round 4
// speedup vs baseline: 3.9809x; 1.1897x over previous
#include <cuda_runtime.h>
#include <math.h>
#include <stdint.h>

#define TOK 4096
#define HID 1024
#define FFN 4096
#define NE  8
#define NPART 64

#define BM 128
#define BN 128
#define BK 32
#define PAD 4
#define KROW (BK + PAD)
#define STAGES 3
#define SMEM_BYTES (2 * STAGES * BM * KROW * 4)   // 110592

// ---------------- device scratch (static; no allocation) ----------------
__device__ float g_probsum_part[NE * NPART];
__device__ int   g_counts_part[NE * NPART];
__device__ int   g_offsets[NE + 1];
__device__ int   g_cursor[NE];
__device__ int   g_perm[TOK];
__device__ int   g_expert[TOK];
__device__ float g_gate[TOK];
// +BM zero rows of padding so GEMM tiles can read past segment ends safely
__device__ float g_xg[(size_t)(TOK + BM) * HID];
__device__ float g_h[(size_t)(TOK + BM) * FFN];

// ---------------- init ----------------
__global__ void init_kernel() {
    int i = blockIdx.x * blockDim.x + threadIdx.x;
    if (i < NE * NPART) { g_probsum_part[i] = 0.f; g_counts_part[i] = 0; }
}

// ---------------- router ----------------
__global__ __launch_bounds__(256) void router_kernel(const float* __restrict__ x,
                                                     const float* __restrict__ rw) {
    int t = blockIdx.x;
    __shared__ float xs[HID];
    __shared__ float lg[NE];
    const float4* x4 = (const float4*)(x + (size_t)t * HID);
    ((float4*)xs)[threadIdx.x] = x4[threadIdx.x];
    __syncthreads();

    int w = threadIdx.x >> 5, lane = threadIdx.x & 31;
    const float* rwe = rw + w * HID;
    float s = 0.f;
    #pragma unroll 8
    for (int i = lane; i < HID; i += 32) s += xs[i] * rwe[i];
    #pragma unroll
    for (int o = 16; o; o >>= 1) s += __shfl_xor_sync(0xffffffffu, s, o);
    if (lane == 0) lg[w] = s;
    __syncthreads();

    if (threadIdx.x == 0) {
        float mx = lg[0]; int idx = 0;
        #pragma unroll
        for (int e = 1; e < NE; e++) if (lg[e] > mx) { mx = lg[e]; idx = e; }
        float p[NE]; float den = 0.f;
        #pragma unroll
        for (int e = 0; e < NE; e++) { p[e] = expf(lg[e] - mx); den += p[e]; }
        float inv = 1.f / den;
        int part = t & (NPART - 1);
        #pragma unroll
        for (int e = 0; e < NE; e++) atomicAdd(&g_probsum_part[e * NPART + part], p[e] * inv);
        g_gate[t] = p[idx] * inv;
        g_expert[t] = idx;
        atomicAdd(&g_counts_part[idx * NPART + part], 1);
    }
}

// ---------------- prefix ----------------
__global__ void prefix_kernel(float* __restrict__ out, int out_size) {
    __shared__ float ps[NE];
    __shared__ int   cs[NE];
    int tid = threadIdx.x;
    if (tid < NE) {
        float s = 0.f; int c = 0;
        for (int p = 0; p < NPART; p++) {
            s += g_probsum_part[tid * NPART + p];
            c += g_counts_part[tid * NPART + p];
        }
        ps[tid] = s; cs[tid] = c;
    }
    __syncthreads();
    if (tid == 0) {
        int run = 0; float aux = 0.f;
        for (int e = 0; e < NE; e++) {
            g_offsets[e] = run; g_cursor[e] = run;
            run += cs[e];
            aux += ps[e] * (float)cs[e];
        }
        g_offsets[NE] = run;
        aux *= 0.01f * (float)NE / ((float)TOK * (float)TOK);
        if (out_size > TOK * HID) out[TOK * HID] = aux;
    }
}

// ---------------- gather ----------------
__global__ __launch_bounds__(256) void gather_kernel(const float* __restrict__ x) {
    int t = blockIdx.x;
    __shared__ int slot_s;
    if (threadIdx.x == 0) {
        int e = g_expert[t];
        int slot = atomicAdd(&g_cursor[e], 1);
        g_perm[slot] = t;
        slot_s = slot;
    }
    __syncthreads();
    int slot = slot_s;
    const float4* src = (const float4*)(x + (size_t)t * HID);
    float4* dst = (float4*)(g_xg + (size_t)slot * HID);
    dst[threadIdx.x] = src[threadIdx.x];
}

// ---------------- helpers ----------------
__device__ __forceinline__ float gelu_exact(float v) {
    return 0.5f * v * (1.0f + erff(v * 0.70710678118654752f));
}
__device__ __forceinline__ uint32_t cvt_tf32(float f) {
    uint32_t u; asm("cvt.rna.tf32.f32 %0, %1;" : "=r"(u) : "f"(f)); return u;
}
__device__ __forceinline__ void cp16(uint32_t saddr, const void* g) {
    asm volatile("cp.async.cg.shared.global [%0], [%1], 16;" :: "r"(saddr), "l"(g));
}
__device__ __forceinline__ void mma_tf32(float c[4], const uint32_t a[4], const uint32_t b[2]) {
    asm volatile("mma.sync.aligned.m16n8k8.row.col.f32.tf32.tf32.f32 "
        "{%0,%1,%2,%3}, {%4,%5,%6,%7}, {%8,%9}, {%0,%1,%2,%3};"
        : "+f"(c[0]), "+f"(c[1]), "+f"(c[2]), "+f"(c[3])
        : "r"(a[0]), "r"(a[1]), "r"(a[2]), "r"(a[3]), "r"(b[0]), "r"(b[1]));
}

// ---------------- grouped tensor-core GEMM (3-stage cp.async pipeline) ----------------
// IS_FC1: A=g_xg [K=HID], B=fc1_w rows, epilogue gelu -> g_h
// else:   A=g_h  [K=FFN], B=fc2_w rows, epilogue gate-scatter -> out
template<int KDIM, bool IS_FC1>
__global__ __launch_bounds__(256, 2) void gemm_tc(const float* __restrict__ W,
                                                  const float* __restrict__ bias,
                                                  float* __restrict__ outp) {
    int e = blockIdx.z;
    int off = g_offsets[e];
    int ne  = g_offsets[e + 1] - off;
    int m0  = blockIdx.y * BM;
    if (m0 >= ne) return;
    int n0 = blockIdx.x * BN;

    const int NDIM = IS_FC1 ? FFN : HID;
    const float* A = (IS_FC1 ? g_xg : g_h) + (size_t)(off + m0) * KDIM;
    const float* B = W + (size_t)e * NDIM * KDIM + (size_t)n0 * KDIM;

    extern __shared__ float sm[];
    float (*As)[BM][KROW] = (float (*)[BM][KROW])sm;
    float (*Bs)[BM][KROW] = (float (*)[BM][KROW])(sm + STAGES * BM * KROW);

    int tid = threadIdx.x;

    // loader mapping: each thread owns 4 A-chunks + 4 B-chunks of 16B per stage
    int rowc[4], kqc[4];
    #pragma unroll
    for (int t = 0; t < 4; t++) { int c = tid + t * 256; rowc[t] = c >> 3; kqc[t] = (c & 7) * 4; }

    uint32_t sAa[4], sBa[4];
    #pragma unroll
    for (int t = 0; t < 4; t++) {
        sAa[t] = (uint32_t)__cvta_generic_to_shared(&As[0][rowc[t]][kqc[t]]);
        sBa[t] = (uint32_t)__cvta_generic_to_shared(&Bs[0][rowc[t]][kqc[t]]);
    }
    const uint32_t STG = BM * KROW * 4;   // stage stride bytes

    const float* Ap[4]; const float* Bp[4];
    #pragma unroll
    for (int t = 0; t < 4; t++) {
        Ap[t] = A + (size_t)rowc[t] * KDIM + kqc[t];
        Bp[t] = B + (size_t)rowc[t] * KDIM + kqc[t];
    }

    // ---- prologue: stages 0,1 ----
    #pragma unroll
    for (int s = 0; s < 2; s++) {
        #pragma unroll
        for (int t = 0; t < 4; t++) {
            cp16(sAa[t] + s * STG, Ap[t] + s * BK);
            cp16(sBa[t] + s * STG, Bp[t] + s * BK);
        }
        asm volatile("cp.async.commit_group;" ::: "memory");
    }

    int wid = tid >> 5, lane = tid & 31;
    int wm = wid & 3;        // m offset wm*32
    int wn = wid >> 2;       // n offset wn*64
    int g  = lane >> 2;
    int t4 = lane & 3;

    float acc[2][8][4] = {};

    const int KT = KDIM / BK;
    int s = 0;
    for (int kt = 0; kt < KT; kt++) {
        asm volatile("cp.async.wait_group 1;" ::: "memory");
        __syncthreads();

        int nk = kt + 2;
        if (nk < KT) {
            int ns = s + 2; if (ns >= STAGES) ns -= STAGES;
            int ko = nk * BK;
            #pragma unroll
            for (int t = 0; t < 4; t++) {
                cp16(sAa[t] + ns * STG, Ap[t] + ko);
                cp16(sBa[t] + ns * STG, Bp[t] + ko);
            }
        }
        asm volatile("cp.async.commit_group;" ::: "memory");

        #pragma unroll
        for (int ks = 0; ks < BK / 8; ks++) {
            int kb = ks * 8;
            uint32_t a[2][4];
            #pragma unroll
            for (int i = 0; i < 2; i++) {
                int rm = wm * 32 + i * 16 + g;
                a[i][0] = cvt_tf32(As[s][rm][kb + t4]);
                a[i][1] = cvt_tf32(As[s][rm + 8][kb + t4]);
                a[i][2] = cvt_tf32(As[s][rm][kb + t4 + 4]);
                a[i][3] = cvt_tf32(As[s][rm + 8][kb + t4 + 4]);
            }
            uint32_t b[8][2];
            #pragma unroll
            for (int j = 0; j < 8; j++) {
                int rn = wn * 64 + j * 8 + g;
                b[j][0] = cvt_tf32(Bs[s][rn][kb + t4]);
                b[j][1] = cvt_tf32(Bs[s][rn][kb + t4 + 4]);
            }
            #pragma unroll
            for (int i = 0; i < 2; i++)
                #pragma unroll
                for (int j = 0; j < 8; j++)
                    mma_tf32(acc[i][j], a[i], b[j]);
        }
        s++; if (s == STAGES) s = 0;
    }

    // ---------------- epilogue ----------------
    #pragma unroll
    for (int i = 0; i < 2; i++) {
        int rml = wm * 32 + i * 16 + g;
        #pragma unroll
        for (int j = 0; j < 8; j++) {
            int col = n0 + wn * 64 + j * 8 + 2 * t4;
            if (IS_FC1) {
                float b0v = bias[(size_t)e * FFN + col];
                float b1v = bias[(size_t)e * FFN + col + 1];
                int m_ = m0 + rml;
                if (m_ < ne) {
                    float2 o;
                    o.x = gelu_exact(acc[i][j][0] + b0v);
                    o.y = gelu_exact(acc[i][j][1] + b1v);
                    *(float2*)&g_h[(size_t)(off + m_) * FFN + col] = o;
                }
                if (m_ + 8 < ne) {
                    float2 o;
                    o.x = gelu_exact(acc[i][j][2] + b0v);
                    o.y = gelu_exact(acc[i][j][3] + b1v);
                    *(float2*)&g_h[(size_t)(off + m_ + 8) * FFN + col] = o;
                }
            } else {
                float b0v = bias[(size_t)e * HID + col];
                float b1v = bias[(size_t)e * HID + col + 1];
                int m_ = m0 + rml;
                if (m_ < ne) {
                    int tok = g_perm[off + m_];
                    float gt = g_gate[tok];
                    float2 o;
                    o.x = (acc[i][j][0] + b0v) * gt;
                    o.y = (acc[i][j][1] + b1v) * gt;
                    *(float2*)&outp[(size_t)tok * HID + col] = o;
                }
                if (m_ + 8 < ne) {
                    int tok = g_perm[off + m_ + 8];
                    float gt = g_gate[tok];
                    float2 o;
                    o.x = (acc[i][j][2] + b0v) * gt;
                    o.y = (acc[i][j][3] + b1v) * gt;
                    *(float2*)&outp[(size_t)tok * HID + col] = o;
                }
            }
        }
    }
}

// ---------------- launch ----------------
extern "C" void kernel_launch(void* const* d_in, const int* in_sizes, int n_in,
                              void* d_out, int out_size) {
    const float* x        = (const float*)d_in[0];
    const float* router_w = (const float*)d_in[1];
    const float* fc1_w    = (const float*)d_in[2];
    const float* fc1_b    = (const float*)d_in[3];
    const float* fc2_w    = (const float*)d_in[4];
    const float* fc2_b    = (const float*)d_in[5];
    float* out = (float*)d_out;

    cudaFuncSetAttribute(gemm_tc<HID, true>,  cudaFuncAttributeMaxDynamicSharedMemorySize, SMEM_BYTES);
    cudaFuncSetAttribute(gemm_tc<FFN, false>, cudaFuncAttributeMaxDynamicSharedMemorySize, SMEM_BYTES);

    init_kernel<<<(NE * NPART + 255) / 256, 256>>>();
    router_kernel<<<TOK, 256>>>(x, router_w);
    prefix_kernel<<<1, 256>>>(out, out_size);
    gather_kernel<<<TOK, 256>>>(x);

    dim3 g1(FFN / BN, TOK / BM, NE);   // 32 x 32 x 8, early-exit tiles
    gemm_tc<HID, true><<<g1, 256, SMEM_BYTES>>>(fc1_w, fc1_b, nullptr);

    dim3 g2(HID / BN, TOK / BM, NE);   // 8 x 32 x 8
    gemm_tc<FFN, false><<<g2, 256, SMEM_BYTES>>>(fc2_w, fc2_b, out);
}

// round 5
// speedup vs baseline: 4.2206x; 1.0602x over previous
#include <cuda_runtime.h>
#include <math.h>
#include <stdint.h>

#define TOK 4096
#define HID 1024
#define FFN 4096
#define NE  8
#define NPART 64

#define BM 128
#define BN 256
#define BK 32
#define PAD 4
#define KROW (BK + PAD)
#define STAGES 3
#define SMEM_BYTES (STAGES * (BM + BN) * KROW * 4)   // 3*384*36*4 = 165888? -> compute: 384*36*4=55296*3=165888

// NOTE: KROW padding applies to both A and B rows.

// ---------------- device scratch (static; no allocation) ----------------
__device__ float g_probsum_part[NE * NPART];
__device__ int   g_counts_part[NE * NPART];
__device__ int   g_offsets[NE + 1];
__device__ int   g_cursor[NE];
__device__ int   g_perm[TOK];
__device__ int   g_expert[TOK];
__device__ float g_gate[TOK];
// +BM zero rows of padding so GEMM tiles can read past segment ends safely
__device__ float g_xg[(size_t)(TOK + BM) * HID];
__device__ float g_h[(size_t)(TOK + BM) * FFN];

// ---------------- init ----------------
__global__ void init_kernel() {
    int i = blockIdx.x * blockDim.x + threadIdx.x;
    if (i < NE * NPART) { g_probsum_part[i] = 0.f; g_counts_part[i] = 0; }
}

// ---------------- router ----------------
__global__ __launch_bounds__(256) void router_kernel(const float* __restrict__ x,
                                                     const float* __restrict__ rw) {
    int t = blockIdx.x;
    __shared__ float xs[HID];
    __shared__ float lg[NE];
    const float4* x4 = (const float4*)(x + (size_t)t * HID);
    ((float4*)xs)[threadIdx.x] = x4[threadIdx.x];
    __syncthreads();

    int w = threadIdx.x >> 5, lane = threadIdx.x & 31;
    const float* rwe = rw + w * HID;
    float s = 0.f;
    #pragma unroll 8
    for (int i = lane; i < HID; i += 32) s += xs[i] * rwe[i];
    #pragma unroll
    for (int o = 16; o; o >>= 1) s += __shfl_xor_sync(0xffffffffu, s, o);
    if (lane == 0) lg[w] = s;
    __syncthreads();

    if (threadIdx.x == 0) {
        float mx = lg[0]; int idx = 0;
        #pragma unroll
        for (int e = 1; e < NE; e++) if (lg[e] > mx) { mx = lg[e]; idx = e; }
        float p[NE]; float den = 0.f;
        #pragma unroll
        for (int e = 0; e < NE; e++) { p[e] = expf(lg[e] - mx); den += p[e]; }
        float inv = 1.f / den;
        int part = t & (NPART - 1);
        #pragma unroll
        for (int e = 0; e < NE; e++) atomicAdd(&g_probsum_part[e * NPART + part], p[e] * inv);
        g_gate[t] = p[idx] * inv;
        g_expert[t] = idx;
        atomicAdd(&g_counts_part[idx * NPART + part], 1);
    }
}

// ---------------- prefix ----------------
__global__ void prefix_kernel(float* __restrict__ out, int out_size) {
    __shared__ float ps[NE];
    __shared__ int   cs[NE];
    int tid = threadIdx.x;
    if (tid < NE) {
        float s = 0.f; int c = 0;
        for (int p = 0; p < NPART; p++) {
            s += g_probsum_part[tid * NPART + p];
            c += g_counts_part[tid * NPART + p];
        }
        ps[tid] = s; cs[tid] = c;
    }
    __syncthreads();
    if (tid == 0) {
        int run = 0; float aux = 0.f;
        for (int e = 0; e < NE; e++) {
            g_offsets[e] = run; g_cursor[e] = run;
            run += cs[e];
            aux += ps[e] * (float)cs[e];
        }
        g_offsets[NE] = run;
        aux *= 0.01f * (float)NE / ((float)TOK * (float)TOK);
        if (out_size > TOK * HID) out[TOK * HID] = aux;
    }
}

// ---------------- gather ----------------
__global__ __launch_bounds__(256) void gather_kernel(const float* __restrict__ x) {
    int t = blockIdx.x;
    __shared__ int slot_s;
    if (threadIdx.x == 0) {
        int e = g_expert[t];
        int slot = atomicAdd(&g_cursor[e], 1);
        g_perm[slot] = t;
        slot_s = slot;
    }
    __syncthreads();
    int slot = slot_s;
    const float4* src = (const float4*)(x + (size_t)t * HID);
    float4* dst = (float4*)(g_xg + (size_t)slot * HID);
    dst[threadIdx.x] = src[threadIdx.x];
}

// ---------------- helpers ----------------
__device__ __forceinline__ float gelu_exact(float v) {
    return 0.5f * v * (1.0f + erff(v * 0.70710678118654752f));
}
__device__ __forceinline__ uint32_t cvt_tf32(float f) {
    uint32_t u; asm("cvt.rna.tf32.f32 %0, %1;" : "=r"(u) : "f"(f)); return u;
}
__device__ __forceinline__ void cp16(uint32_t saddr, const void* g) {
    asm volatile("cp.async.cg.shared.global [%0], [%1], 16;" :: "r"(saddr), "l"(g));
}
__device__ __forceinline__ void mma_tf32(float c[4], const uint32_t a[4], const uint32_t b[2]) {
    asm volatile("mma.sync.aligned.m16n8k8.row.col.f32.tf32.tf32.f32 "
        "{%0,%1,%2,%3}, {%4,%5,%6,%7}, {%8,%9}, {%0,%1,%2,%3};"
        : "+f"(c[0]), "+f"(c[1]), "+f"(c[2]), "+f"(c[3])
        : "r"(a[0]), "r"(a[1]), "r"(a[2]), "r"(a[3]), "r"(b[0]), "r"(b[1]));
}

// ---------------- grouped tensor-core GEMM (3-stage pipeline, 64x64 warp tiles) ----------------
// CTA tile 128x256. 8 warps in 2x4 grid, each computing 64x64.
template<int KDIM, bool IS_FC1>
__global__ __launch_bounds__(256, 1) void gemm_tc(const float* __restrict__ W,
                                                  const float* __restrict__ bias,
                                                  float* __restrict__ outp) {
    int e = blockIdx.z;
    int off = g_offsets[e];
    int ne  = g_offsets[e + 1] - off;
    int m0  = blockIdx.y * BM;
    if (m0 >= ne) return;
    int n0 = blockIdx.x * BN;

    const int NDIM = IS_FC1 ? FFN : HID;
    const float* A = (IS_FC1 ? g_xg : g_h) + (size_t)(off + m0) * KDIM;
    const float* B = W + (size_t)e * NDIM * KDIM + (size_t)n0 * KDIM;

    extern __shared__ float sm[];
    float (*As)[BM][KROW] = (float (*)[BM][KROW])sm;                       // STAGES x BM x KROW
    float (*Bs)[BN][KROW] = (float (*)[BN][KROW])(sm + STAGES * BM * KROW);

    int tid = threadIdx.x;

    // loader mapping: A = 1024 16B-chunks (4/thread), B = 2048 chunks (8/thread)
    int rA[4], kA[4];
    #pragma unroll
    for (int t = 0; t < 4; t++) { int c = tid + t * 256; rA[t] = c >> 3; kA[t] = (c & 7) * 4; }
    int rB[8], kB[8];
    #pragma unroll
    for (int t = 0; t < 8; t++) { int c = tid + t * 256; rB[t] = c >> 3; kB[t] = (c & 7) * 4; }

    uint32_t sAa[4], sBa[8];
    #pragma unroll
    for (int t = 0; t < 4; t++) sAa[t] = (uint32_t)__cvta_generic_to_shared(&As[0][rA[t]][kA[t]]);
    #pragma unroll
    for (int t = 0; t < 8; t++) sBa[t] = (uint32_t)__cvta_generic_to_shared(&Bs[0][rB[t]][kB[t]]);
    const uint32_t STG_A = BM * KROW * 4;
    const uint32_t STG_B = BN * KROW * 4;

    const float* Ap[4]; const float* Bp[8];
    #pragma unroll
    for (int t = 0; t < 4; t++) Ap[t] = A + (size_t)rA[t] * KDIM + kA[t];
    #pragma unroll
    for (int t = 0; t < 8; t++) Bp[t] = B + (size_t)rB[t] * KDIM + kB[t];

    // ---- prologue: stages 0,1 ----
    #pragma unroll
    for (int s = 0; s < 2; s++) {
        #pragma unroll
        for (int t = 0; t < 4; t++) cp16(sAa[t] + s * STG_A, Ap[t] + s * BK);
        #pragma unroll
        for (int t = 0; t < 8; t++) cp16(sBa[t] + s * STG_B, Bp[t] + s * BK);
        asm volatile("cp.async.commit_group;" ::: "memory");
    }

    int wid = tid >> 5, lane = tid & 31;
    int wm = wid & 1;        // m offset wm*64
    int wn = wid >> 1;       // n offset wn*64
    int g  = lane >> 2;
    int t4 = lane & 3;

    float acc[4][8][4] = {};   // 4 m16-tiles x 8 n8-tiles

    const int KT = KDIM / BK;
    int s = 0;
    for (int kt = 0; kt < KT; kt++) {
        asm volatile("cp.async.wait_group 1;" ::: "memory");
        __syncthreads();

        int nk = kt + 2;
        if (nk < KT) {
            int ns = s + 2; if (ns >= STAGES) ns -= STAGES;
            int ko = nk * BK;
            #pragma unroll
            for (int t = 0; t < 4; t++) cp16(sAa[t] + ns * STG_A, Ap[t] + ko);
            #pragma unroll
            for (int t = 0; t < 8; t++) cp16(sBa[t] + ns * STG_B, Bp[t] + ko);
        }
        asm volatile("cp.async.commit_group;" ::: "memory");

        #pragma unroll
        for (int ks = 0; ks < BK / 8; ks++) {
            int kb = ks * 8;
            uint32_t a[4][4];
            #pragma unroll
            for (int i = 0; i < 4; i++) {
                int rm = wm * 64 + i * 16 + g;
                a[i][0] = cvt_tf32(As[s][rm][kb + t4]);
                a[i][1] = cvt_tf32(As[s][rm + 8][kb + t4]);
                a[i][2] = cvt_tf32(As[s][rm][kb + t4 + 4]);
                a[i][3] = cvt_tf32(As[s][rm + 8][kb + t4 + 4]);
            }
            uint32_t b[8][2];
            #pragma unroll
            for (int j = 0; j < 8; j++) {
                int rn = wn * 64 + j * 8 + g;
                b[j][0] = cvt_tf32(Bs[s][rn][kb + t4]);
                b[j][1] = cvt_tf32(Bs[s][rn][kb + t4 + 4]);
            }
            #pragma unroll
            for (int i = 0; i < 4; i++)
                #pragma unroll
                for (int j = 0; j < 8; j++)
                    mma_tf32(acc[i][j], a[i], b[j]);
        }
        s++; if (s == STAGES) s = 0;
    }

    // ---------------- epilogue ----------------
    #pragma unroll
    for (int i = 0; i < 4; i++) {
        int rml = wm * 64 + i * 16 + g;
        #pragma unroll
        for (int j = 0; j < 8; j++) {
            int col = n0 + wn * 64 + j * 8 + 2 * t4;
            if (IS_FC1) {
                float b0v = bias[(size_t)e * FFN + col];
                float b1v = bias[(size_t)e * FFN + col + 1];
                int m_ = m0 + rml;
                if (m_ < ne) {
                    float2 o;
                    o.x = gelu_exact(acc[i][j][0] + b0v);
                    o.y = gelu_exact(acc[i][j][1] + b1v);
                    *(float2*)&g_h[(size_t)(off + m_) * FFN + col] = o;
                }
                if (m_ + 8 < ne) {
                    float2 o;
                    o.x = gelu_exact(acc[i][j][2] + b0v);
                    o.y = gelu_exact(acc[i][j][3] + b1v);
                    *(float2*)&g_h[(size_t)(off + m_ + 8) * FFN + col] = o;
                }
            } else {
                float b0v = bias[(size_t)e * HID + col];
                float b1v = bias[(size_t)e * HID + col + 1];
                int m_ = m0 + rml;
                if (m_ < ne) {
                    int tok = g_perm[off + m_];
                    float gt = g_gate[tok];
                    float2 o;
                    o.x = (acc[i][j][0] + b0v) * gt;
                    o.y = (acc[i][j][1] + b1v) * gt;
                    *(float2*)&outp[(size_t)tok * HID + col] = o;
                }
                if (m_ + 8 < ne) {
                    int tok = g_perm[off + m_ + 8];
                    float gt = g_gate[tok];
                    float2 o;
                    o.x = (acc[i][j][2] + b0v) * gt;
                    o.y = (acc[i][j][3] + b1v) * gt;
                    *(float2*)&outp[(size_t)tok * HID + col] = o;
                }
            }
        }
    }
}

// ---------------- launch ----------------
extern "C" void kernel_launch(void* const* d_in, const int* in_sizes, int n_in,
                              void* d_out, int out_size) {
    const float* x        = (const float*)d_in[0];
    const float* router_w = (const float*)d_in[1];
    const float* fc1_w    = (const float*)d_in[2];
    const float* fc1_b    = (const float*)d_in[3];
    const float* fc2_w    = (const float*)d_in[4];
    const float* fc2_b    = (const float*)d_in[5];
    float* out = (float*)d_out;

    cudaFuncSetAttribute(gemm_tc<HID, true>,  cudaFuncAttributeMaxDynamicSharedMemorySize, SMEM_BYTES);
    cudaFuncSetAttribute(gemm_tc<FFN, false>, cudaFuncAttributeMaxDynamicSharedMemorySize, SMEM_BYTES);

    init_kernel<<<(NE * NPART + 255) / 256, 256>>>();
    router_kernel<<<TOK, 256>>>(x, router_w);
    prefix_kernel<<<1, 256>>>(out, out_size);
    gather_kernel<<<TOK, 256>>>(x);

    dim3 g1(FFN / BN, TOK / BM, NE);   // 16 x 32 x 8, early-exit tiles
    gemm_tc<HID, true><<<g1, 256, SMEM_BYTES>>>(fc1_w, fc1_b, nullptr);

    dim3 g2(HID / BN, TOK / BM, NE);   // 4 x 32 x 8
    gemm_tc<FFN, false><<<g2, 256, SMEM_BYTES>>>(fc2_w, fc2_b, out);
}